// round 5
// baseline (speedup 1.0000x reference)
#include <cuda_runtime.h>
#include <cuda_fp16.h>
#include <cstdint>

// Problem shapes (fixed for this dataset instance)
#define T_DIM 8192
#define N_DIM 4096
#define M_DIM 16384

// Scratch (device globals: allocation-free per harness rules)
__device__ __half g_t[(size_t)T_DIM * N_DIM];   // 64 MB  : t = fwht(x*SV)/sqrt(N), fp16
__device__ __half g_W[(size_t)M_DIM * N_DIM];   // 128 MB : decoded W_hat, fp16
__device__ __half g_z[(size_t)T_DIM * M_DIM];   // 256 MB : z = t @ W^T, fp16

// ---------------------------------------------------------------------------
// PTX helpers (sm_80-era instructions only: legal on plain sm_103)
// ---------------------------------------------------------------------------
__device__ __forceinline__ uint32_t smem_u32(const void* p) {
    uint32_t a;
    asm("{ .reg .u64 t; cvta.to.shared.u64 t, %1; cvt.u32.u64 %0, t; }" : "=r"(a) : "l"(p));
    return a;
}

__device__ __forceinline__ void cp16(uint32_t dst, const void* src) {
    asm volatile("cp.async.cg.shared.global [%0], [%1], 16;" :: "r"(dst), "l"(src) : "memory");
}
#define CP_COMMIT() asm volatile("cp.async.commit_group;" ::: "memory")
#define CP_WAIT(n)  asm volatile("cp.async.wait_group %0;" :: "n"(n) : "memory")

#define LDSM4(r0, r1, r2, r3, addr) \
    asm volatile("ldmatrix.sync.aligned.m8n8.x4.shared.b16 {%0,%1,%2,%3}, [%4];" \
                 : "=r"(r0), "=r"(r1), "=r"(r2), "=r"(r3) : "r"(addr))

#define MMA16816(d, a, b) \
    asm volatile("mma.sync.aligned.m16n8k16.row.col.f32.f16.f16.f32 " \
                 "{%0,%1,%2,%3}, {%4,%5,%6,%7}, {%8,%9}, {%0,%1,%2,%3};" \
                 : "+f"((d)[0]), "+f"((d)[1]), "+f"((d)[2]), "+f"((d)[3]) \
                 : "r"((a)[0]), "r"((a)[1]), "r"((a)[2]), "r"((a)[3]), \
                   "r"((b)[0]), "r"((b)[1]))

// In-register 16-point FWHT
__device__ __forceinline__ void fwht16(float* v) {
#pragma unroll
    for (int h = 1; h < 16; h <<= 1) {
#pragma unroll
        for (int j = 0; j < 16; j++) {
            if ((j & h) == 0) {
                float a = v[j], b = v[j + h];
                v[j] = a + b;
                v[j + h] = a - b;
            }
        }
    }
}

__device__ __forceinline__ int skew(int i) { return i + (i >> 4); }

// ---------------------------------------------------------------------------
// 1) Decode W_hat = cb1[Q1] + irs * cb2[Q2]  (row-major fp16)
// ---------------------------------------------------------------------------
__global__ void decode_kernel(const int* __restrict__ Q1, const int* __restrict__ Q2,
                              const float* __restrict__ cb1, const float* __restrict__ cb2,
                              const float* __restrict__ irs_p,
                              __half* __restrict__ W, int total)
{
    int i = blockIdx.x * blockDim.x + threadIdx.x;
    if (i >= total) return;
    float irs = __ldg(irs_p);
    int q1 = __ldg(&Q1[i]);
    int q2 = __ldg(&Q2[i]);
    const float4* c1 = reinterpret_cast<const float4*>(cb1 + (size_t)q1 * 8);
    const float4* c2 = reinterpret_cast<const float4*>(cb2 + (size_t)q2 * 8);
    float4 a0 = c1[0], a1 = c1[1];
    float4 b0 = c2[0], b1 = c2[1];
    __half2 h0 = __floats2half2_rn(a0.x + irs * b0.x, a0.y + irs * b0.y);
    __half2 h1 = __floats2half2_rn(a0.z + irs * b0.z, a0.w + irs * b0.w);
    __half2 h2 = __floats2half2_rn(a1.x + irs * b1.x, a1.y + irs * b1.y);
    __half2 h3 = __floats2half2_rn(a1.z + irs * b1.z, a1.w + irs * b1.w);
    uint4 u;
    u.x = *reinterpret_cast<unsigned*>(&h0);
    u.y = *reinterpret_cast<unsigned*>(&h1);
    u.z = *reinterpret_cast<unsigned*>(&h2);
    u.w = *reinterpret_cast<unsigned*>(&h3);
    *reinterpret_cast<uint4*>(W + (size_t)i * 8) = u;
}

// ---------------------------------------------------------------------------
// 2) t = fwht(x * SV) / sqrt(N): 256 threads x 16 elems (radix-16^3)
// ---------------------------------------------------------------------------
__global__ void __launch_bounds__(256)
fwht_x_kernel(const float* __restrict__ x, const float* __restrict__ SV,
              __half* __restrict__ t)
{
    __shared__ float s[4096 + 256];
    const int g = threadIdx.x;
    const int row = blockIdx.x;
    const float* xr = x + (size_t)row * N_DIM;
    float v[16];

#pragma unroll
    for (int j = 0; j < 16; j++) v[j] = xr[g * 16 + j] * SV[g * 16 + j];
    fwht16(v);
#pragma unroll
    for (int j = 0; j < 16; j++) s[skew(g * 16 + j)] = v[j];
    __syncthreads();

    {
        int base = (g >> 4) * 256 + (g & 15);
#pragma unroll
        for (int j = 0; j < 16; j++) v[j] = s[skew(base + j * 16)];
        fwht16(v);
#pragma unroll
        for (int j = 0; j < 16; j++) s[skew(base + j * 16)] = v[j];
    }
    __syncthreads();

    {
        float sc = 1.0f / sqrtf((float)N_DIM);
#pragma unroll
        for (int j = 0; j < 16; j++) v[j] = s[skew(g + j * 256)];
        fwht16(v);
        __half* tr = t + (size_t)row * N_DIM;
#pragma unroll
        for (int j = 0; j < 16; j++) tr[g + j * 256] = __float2half(v[j] * sc);
    }
}

// ---------------------------------------------------------------------------
// 3) GEMM: z[T,M] = t @ W^T (fp16 out). Block 128x256x64, warp tile 64x64,
//    3-stage cp.async, XOR-swizzled smem + ldmatrix. 8 warps.
// ---------------------------------------------------------------------------
#define BM 128
#define BN 256
#define BK 64
#define STAGES 3
#define NKC (N_DIM / BK)   // 64
// smem (uint4 units): A stage st at st*1024 (+r*8+c), B stage st at 3072+st*2048
#define AOFF(st) ((st) * 1024)
#define BOFF(st) (3072 + (st) * 2048)

__global__ void __launch_bounds__(256, 1)
gemm_mma_kernel(const __half* __restrict__ A, const __half* __restrict__ B,
                __half* __restrict__ C)
{
    extern __shared__ uint4 smem4[];
    const uint32_t sbase = smem_u32(smem4);

    const int tid = threadIdx.x;
    const int wid = tid >> 5;
    const int lane = tid & 31;
    const int bm = blockIdx.x * BM;   // T dimension (A L2-resident)
    const int bn = blockIdx.y * BN;   // M dimension

    const int wm = (wid >> 2) * 64;   // warp row offset: 0/64
    const int wn = (wid & 3) * 64;    // warp col offset: 0/64/128/192

    float acc[4][8][4];
#pragma unroll
    for (int i = 0; i < 4; i++)
#pragma unroll
        for (int j = 0; j < 8; j++)
#pragma unroll
            for (int q = 0; q < 4; q++) acc[i][j][q] = 0.0f;

    const int lrow = tid >> 3;        // 0..31
    const int lc = tid & 7;           // 16B chunk within 128B row
    const __half* Ab = A + (size_t)bm * N_DIM + lc * 8;
    const __half* Bb = B + (size_t)bn * N_DIM + lc * 8;

    auto issue_stage = [&](int kc) {
        int st = kc % STAGES;
        const __half* Ag = Ab + kc * BK;
        const __half* Bg = Bb + kc * BK;
#pragma unroll
        for (int p = 0; p < 4; p++) {
            int r = lrow + p * 32;
            int cc = lc ^ (r & 7);
            cp16(sbase + ((AOFF(st) + r * 8 + cc) << 4), Ag + (size_t)r * N_DIM);
        }
#pragma unroll
        for (int p = 0; p < 8; p++) {
            int r = lrow + p * 32;
            int cc = lc ^ (r & 7);
            cp16(sbase + ((BOFF(st) + r * 8 + cc) << 4), Bg + (size_t)r * N_DIM);
        }
        CP_COMMIT();
    };

    issue_stage(0);
    issue_stage(1);

    const int ra = wm + (lane & 15);                         // A row base
    const int ca = (lane >> 4);                              // A chunk bit
    const int rb = wn + (lane & 7) + ((lane & 16) ? 8 : 0);  // B row base
    const int cb = (lane >> 3) & 1;                          // B chunk bit

    for (int kc = 0; kc < NKC; kc++) {
        CP_WAIT(1);
        __syncthreads();

        if (kc + 2 < NKC) issue_stage(kc + 2);
        else CP_COMMIT();

        const int st = kc % STAGES;

#pragma unroll
        for (int kk = 0; kk < 4; kk++) {
            uint32_t a[4][4];
            uint32_t b[8][2];
#pragma unroll
            for (int mi = 0; mi < 4; mi++) {
                int r = ra + mi * 16;
                int c = (kk * 2 + ca) ^ (r & 7);
                LDSM4(a[mi][0], a[mi][1], a[mi][2], a[mi][3],
                      sbase + ((AOFF(st) + r * 8 + c) << 4));
            }
#pragma unroll
            for (int njp = 0; njp < 4; njp++) {
                int r = rb + njp * 16;
                int c = (kk * 2 + cb) ^ (r & 7);
                uint32_t t0, t1, t2, t3;
                LDSM4(t0, t1, t2, t3, sbase + ((BOFF(st) + r * 8 + c) << 4));
                b[njp * 2 + 0][0] = t0;  b[njp * 2 + 0][1] = t1;
                b[njp * 2 + 1][0] = t2;  b[njp * 2 + 1][1] = t3;
            }
#pragma unroll
            for (int mi = 0; mi < 4; mi++)
#pragma unroll
                for (int nj = 0; nj < 8; nj++)
                    MMA16816(acc[mi][nj], a[mi], b[nj]);
        }
    }

    // epilogue: fp16 stores (one half2 per fragment row-half)
    const int er = lane >> 2;
    const int ec = (lane & 3) * 2;
#pragma unroll
    for (int mi = 0; mi < 4; mi++) {
#pragma unroll
        for (int nj = 0; nj < 8; nj++) {
            size_t r0 = (size_t)(bm + wm + mi * 16 + er) * M_DIM + (bn + wn + nj * 8 + ec);
            size_t r1 = r0 + (size_t)8 * M_DIM;
            __half2 v0 = __floats2half2_rn(acc[mi][nj][0], acc[mi][nj][1]);
            __half2 v1 = __floats2half2_rn(acc[mi][nj][2], acc[mi][nj][3]);
            __stcs(reinterpret_cast<__half2*>(C + r0), v0);
            __stcs(reinterpret_cast<__half2*>(C + r1), v1);
        }
    }
}

// ---------------------------------------------------------------------------
// 4) y = fwht(z)/sqrt(M) * SU * Wscale. Reads fp16 z, writes fp32 y.
//    1024 threads x 16 elems; radix-16 x3 + radix-4.
// ---------------------------------------------------------------------------
__global__ void __launch_bounds__(1024)
fwht_y_kernel(const __half* __restrict__ z, float* __restrict__ y,
              const float* __restrict__ SU, const float* __restrict__ Wscale_p)
{
    extern __shared__ float s[];   // 16384 + 1024 floats (skewed)
    const int g = threadIdx.x;
    const int row = blockIdx.x;
    const __half2* zr = reinterpret_cast<const __half2*>(z + (size_t)row * M_DIM);
    float* yr = y + (size_t)row * M_DIM;
    float v[16];

    // round 1: stride 1, from gmem (fp16 -> fp32)
#pragma unroll
    for (int j = 0; j < 8; j++) {
        float2 f = __half22float2(zr[g * 8 + j]);
        v[2 * j] = f.x;
        v[2 * j + 1] = f.y;
    }
    fwht16(v);
#pragma unroll
    for (int j = 0; j < 16; j++) s[skew(g * 16 + j)] = v[j];
    __syncthreads();

    // round 2: stride 16
    {
        int base = (g >> 4) * 256 + (g & 15);
#pragma unroll
        for (int j = 0; j < 16; j++) v[j] = s[skew(base + j * 16)];
        fwht16(v);
#pragma unroll
        for (int j = 0; j < 16; j++) s[skew(base + j * 16)] = v[j];
    }
    __syncthreads();

    // round 3: stride 256
    {
        int base = (g >> 8) * 4096 + (g & 255);
#pragma unroll
        for (int j = 0; j < 16; j++) v[j] = s[skew(base + j * 256)];
        fwht16(v);
#pragma unroll
        for (int j = 0; j < 16; j++) s[skew(base + j * 256)] = v[j];
    }
    __syncthreads();

    // round 4: radix-4 at stride 4096, scale + write out
    float scb = (1.0f / sqrtf((float)M_DIM)) * __ldg(Wscale_p);
#pragma unroll
    for (int q = 0; q < 4; q++) {
        int idx = g + q * 1024;
        float a = s[skew(idx)];
        float b = s[skew(idx + 4096)];
        float c = s[skew(idx + 8192)];
        float d = s[skew(idx + 12288)];
        yr[idx]         = (a + b + c + d) * scb * SU[idx];
        yr[idx + 4096]  = (a - b + c - d) * scb * SU[idx + 4096];
        yr[idx + 8192]  = (a + b - c - d) * scb * SU[idx + 8192];
        yr[idx + 12288] = (a - b - c + d) * scb * SU[idx + 12288];
    }
}

// ---------------------------------------------------------------------------
// Launch
// ---------------------------------------------------------------------------
extern "C" void kernel_launch(void* const* d_in, const int* in_sizes, int n_in,
                              void* d_out, int out_size)
{
    const float* x   = (const float*)d_in[0];
    const int*   Q1  = (const int*)d_in[1];
    const int*   Q2  = (const int*)d_in[2];
    const float* SU  = (const float*)d_in[3];
    const float* SV  = (const float*)d_in[4];
    const float* cb1 = (const float*)d_in[5];
    const float* cb2 = (const float*)d_in[6];
    const float* Wsc = (const float*)d_in[7];
    const float* irs = (const float*)d_in[8];
    float* out = (float*)d_out;

    __half *t_p, *W_p, *z_p;
    cudaGetSymbolAddress((void**)&t_p, g_t);
    cudaGetSymbolAddress((void**)&W_p, g_W);
    cudaGetSymbolAddress((void**)&z_p, g_z);

    // 1) decode weights
    int total = M_DIM * (N_DIM / 8);
    decode_kernel<<<(total + 255) / 256, 256>>>(Q1, Q2, cb1, cb2, irs, W_p, total);

    // 2) input Hadamard transform
    fwht_x_kernel<<<T_DIM, 256>>>(x, SV, t_p);

    // 3) GEMM into fp16 z (144 KB dynamic smem)
    int gemm_smem = (STAGES * 1024 + STAGES * 2048) * (int)sizeof(uint4);
    cudaFuncSetAttribute(gemm_mma_kernel,
                         cudaFuncAttributeMaxDynamicSharedMemorySize, gemm_smem);
    dim3 grid(T_DIM / BM, M_DIM / BN);
    gemm_mma_kernel<<<grid, 256, gemm_smem>>>(t_p, W_p, z_p);

    // 4) output Hadamard + scaling into d_out
    int ysmem = (M_DIM + 1024) * (int)sizeof(float);
    cudaFuncSetAttribute(fwht_y_kernel,
                         cudaFuncAttributeMaxDynamicSharedMemorySize, ysmem);
    fwht_y_kernel<<<T_DIM, 1024, ysmem>>>(z_p, out, SU, Wsc);
}

// round 6
// speedup vs baseline: 1.0922x; 1.0922x over previous
#include <cuda_runtime.h>
#include <cuda_fp16.h>
#include <cstdint>

// Problem shapes (fixed for this dataset instance)
#define T_DIM 8192
#define N_DIM 4096
#define M_DIM 16384

// Scratch (device globals: allocation-free per harness rules)
__device__ __half g_t[(size_t)T_DIM * N_DIM];   // 64 MB  : t = fwht(x*SV)/sqrt(N), fp16
__device__ __half g_W[(size_t)M_DIM * N_DIM];   // 128 MB : decoded W_hat, fp16
__device__ __half g_z[(size_t)T_DIM * M_DIM];   // 256 MB : z = t @ W^T, fp16

// ---------------------------------------------------------------------------
// PTX helpers (sm_80-era instructions only: legal on plain sm_103)
// ---------------------------------------------------------------------------
__device__ __forceinline__ uint32_t smem_u32(const void* p) {
    uint32_t a;
    asm("{ .reg .u64 t; cvta.to.shared.u64 t, %1; cvt.u32.u64 %0, t; }" : "=r"(a) : "l"(p));
    return a;
}

__device__ __forceinline__ void cp16(uint32_t dst, const void* src) {
    asm volatile("cp.async.cg.shared.global [%0], [%1], 16;" :: "r"(dst), "l"(src) : "memory");
}
#define CP_COMMIT() asm volatile("cp.async.commit_group;" ::: "memory")
#define CP_WAIT(n)  asm volatile("cp.async.wait_group %0;" :: "n"(n) : "memory")

#define LDSM4(r0, r1, r2, r3, addr) \
    asm volatile("ldmatrix.sync.aligned.m8n8.x4.shared.b16 {%0,%1,%2,%3}, [%4];" \
                 : "=r"(r0), "=r"(r1), "=r"(r2), "=r"(r3) : "r"(addr))

#define MMA16816(d, a, b) \
    asm volatile("mma.sync.aligned.m16n8k16.row.col.f32.f16.f16.f32 " \
                 "{%0,%1,%2,%3}, {%4,%5,%6,%7}, {%8,%9}, {%0,%1,%2,%3};" \
                 : "+f"((d)[0]), "+f"((d)[1]), "+f"((d)[2]), "+f"((d)[3]) \
                 : "r"((a)[0]), "r"((a)[1]), "r"((a)[2]), "r"((a)[3]), \
                   "r"((b)[0]), "r"((b)[1]))

// In-register 16-point FWHT
__device__ __forceinline__ void fwht16(float* v) {
#pragma unroll
    for (int h = 1; h < 16; h <<= 1) {
#pragma unroll
        for (int j = 0; j < 16; j++) {
            if ((j & h) == 0) {
                float a = v[j], b = v[j + h];
                v[j] = a + b;
                v[j + h] = a - b;
            }
        }
    }
}

__device__ __forceinline__ int skew(int i) { return i + (i >> 4); }

// ---------------------------------------------------------------------------
// 1) Decode W_hat = cb1[Q1] + irs * cb2[Q2]  (row-major fp16)
// ---------------------------------------------------------------------------
__global__ void decode_kernel(const int* __restrict__ Q1, const int* __restrict__ Q2,
                              const float* __restrict__ cb1, const float* __restrict__ cb2,
                              const float* __restrict__ irs_p,
                              __half* __restrict__ W, int total)
{
    int i = blockIdx.x * blockDim.x + threadIdx.x;
    if (i >= total) return;
    float irs = __ldg(irs_p);
    int q1 = __ldg(&Q1[i]);
    int q2 = __ldg(&Q2[i]);
    const float4* c1 = reinterpret_cast<const float4*>(cb1 + (size_t)q1 * 8);
    const float4* c2 = reinterpret_cast<const float4*>(cb2 + (size_t)q2 * 8);
    float4 a0 = c1[0], a1 = c1[1];
    float4 b0 = c2[0], b1 = c2[1];
    __half2 h0 = __floats2half2_rn(a0.x + irs * b0.x, a0.y + irs * b0.y);
    __half2 h1 = __floats2half2_rn(a0.z + irs * b0.z, a0.w + irs * b0.w);
    __half2 h2 = __floats2half2_rn(a1.x + irs * b1.x, a1.y + irs * b1.y);
    __half2 h3 = __floats2half2_rn(a1.z + irs * b1.z, a1.w + irs * b1.w);
    uint4 u;
    u.x = *reinterpret_cast<unsigned*>(&h0);
    u.y = *reinterpret_cast<unsigned*>(&h1);
    u.z = *reinterpret_cast<unsigned*>(&h2);
    u.w = *reinterpret_cast<unsigned*>(&h3);
    *reinterpret_cast<uint4*>(W + (size_t)i * 8) = u;
}

// ---------------------------------------------------------------------------
// 2) t = fwht(x * SV) / sqrt(N): 256 threads x 16 elems (radix-16^3)
// ---------------------------------------------------------------------------
__global__ void __launch_bounds__(256)
fwht_x_kernel(const float* __restrict__ x, const float* __restrict__ SV,
              __half* __restrict__ t)
{
    __shared__ float s[4096 + 256];
    const int g = threadIdx.x;
    const int row = blockIdx.x;
    const float* xr = x + (size_t)row * N_DIM;
    float v[16];

#pragma unroll
    for (int j = 0; j < 16; j++) v[j] = xr[g * 16 + j] * SV[g * 16 + j];
    fwht16(v);
#pragma unroll
    for (int j = 0; j < 16; j++) s[skew(g * 16 + j)] = v[j];
    __syncthreads();

    {
        int base = (g >> 4) * 256 + (g & 15);
#pragma unroll
        for (int j = 0; j < 16; j++) v[j] = s[skew(base + j * 16)];
        fwht16(v);
#pragma unroll
        for (int j = 0; j < 16; j++) s[skew(base + j * 16)] = v[j];
    }
    __syncthreads();

    {
        float sc = 1.0f / sqrtf((float)N_DIM);
#pragma unroll
        for (int j = 0; j < 16; j++) v[j] = s[skew(g + j * 256)];
        fwht16(v);
        __half* tr = t + (size_t)row * N_DIM;
#pragma unroll
        for (int j = 0; j < 16; j++) tr[g + j * 256] = __float2half(v[j] * sc);
    }
}

// ---------------------------------------------------------------------------
// 3) GEMM: z[T,M] = t @ W^T (fp16 out). Block 128x128x64, warp tile 64x32,
//    3-stage cp.async (96 KB smem -> 2 CTAs/SM), XOR-swizzle + ldmatrix.
// ---------------------------------------------------------------------------
#define BM 128
#define BN 128
#define BK 64
#define STAGES 3
#define NKC (N_DIM / BK)   // 64

__global__ void __launch_bounds__(256, 2)
gemm_mma_kernel(const __half* __restrict__ A, const __half* __restrict__ B,
                __half* __restrict__ C)
{
    // smem in uint4 units: As[STAGES][128][8], Bs[STAGES][128][8]
    extern __shared__ uint4 smem4[];
    const uint32_t sbase = smem_u32(smem4);

    const int tid = threadIdx.x;
    const int wid = tid >> 5;
    const int lane = tid & 31;
    const int bm = blockIdx.x * BM;   // T dimension (A L2-resident)
    const int bn = blockIdx.y * BN;   // M dimension

    const int wm = (wid >> 2) * 64;   // warp row offset: 0/64
    const int wn = (wid & 3) * 32;    // warp col offset: 0..96

    float acc[4][4][4];
#pragma unroll
    for (int i = 0; i < 4; i++)
#pragma unroll
        for (int j = 0; j < 4; j++)
#pragma unroll
            for (int q = 0; q < 4; q++) acc[i][j][q] = 0.0f;

    const int lrow = tid >> 3;
    const int lc = tid & 7;
    const __half* Ab = A + (size_t)bm * N_DIM + lc * 8;
    const __half* Bb = B + (size_t)bn * N_DIM + lc * 8;

    auto issue_stage = [&](int kc) {
        int st = kc % STAGES;
        const __half* Ag = Ab + kc * BK;
        const __half* Bg = Bb + kc * BK;
#pragma unroll
        for (int p = 0; p < 4; p++) {
            int r = lrow + p * 32;
            int cc = lc ^ (r & 7);
            uint32_t da = sbase + ((st * 1024 + r * 8 + cc) << 4);
            uint32_t db = sbase + (((STAGES + st) * 1024 + r * 8 + cc) << 4);
            cp16(da, Ag + (size_t)r * N_DIM);
            cp16(db, Bg + (size_t)r * N_DIM);
        }
        CP_COMMIT();
    };

    issue_stage(0);
    issue_stage(1);

    const int ra = wm + (lane & 15);
    const int ca = (lane >> 4);
    const int rb = wn + (lane & 7) + ((lane & 16) ? 8 : 0);
    const int cb = (lane >> 3) & 1;

    for (int kc = 0; kc < NKC; kc++) {
        CP_WAIT(1);
        __syncthreads();

        if (kc + 2 < NKC) issue_stage(kc + 2);
        else CP_COMMIT();

        const int st = kc % STAGES;
        const uint32_t abase = sbase + ((st * 1024) << 4);
        const uint32_t bbase = sbase + (((STAGES + st) * 1024) << 4);

#pragma unroll
        for (int kk = 0; kk < 4; kk++) {
            uint32_t a[4][4];
            uint32_t b[4][2];
#pragma unroll
            for (int mi = 0; mi < 4; mi++) {
                int r = ra + mi * 16;
                int c = (kk * 2 + ca) ^ (r & 7);
                LDSM4(a[mi][0], a[mi][1], a[mi][2], a[mi][3],
                      abase + ((r * 8 + c) << 4));
            }
#pragma unroll
            for (int njp = 0; njp < 2; njp++) {
                int r = rb + njp * 16;
                int c = (kk * 2 + cb) ^ (r & 7);
                uint32_t t0, t1, t2, t3;
                LDSM4(t0, t1, t2, t3, bbase + ((r * 8 + c) << 4));
                b[njp * 2 + 0][0] = t0;  b[njp * 2 + 0][1] = t1;
                b[njp * 2 + 1][0] = t2;  b[njp * 2 + 1][1] = t3;
            }
#pragma unroll
            for (int mi = 0; mi < 4; mi++)
#pragma unroll
                for (int nj = 0; nj < 4; nj++)
                    MMA16816(acc[mi][nj], a[mi], b[nj]);
        }
    }

    // epilogue: fp16 stores (one half2 per fragment row-half)
    const int er = lane >> 2;
    const int ec = (lane & 3) * 2;
#pragma unroll
    for (int mi = 0; mi < 4; mi++) {
#pragma unroll
        for (int nj = 0; nj < 4; nj++) {
            size_t r0 = (size_t)(bm + wm + mi * 16 + er) * M_DIM + (bn + wn + nj * 8 + ec);
            size_t r1 = r0 + (size_t)8 * M_DIM;
            __half2 v0 = __floats2half2_rn(acc[mi][nj][0], acc[mi][nj][1]);
            __half2 v1 = __floats2half2_rn(acc[mi][nj][2], acc[mi][nj][3]);
            __stcs(reinterpret_cast<__half2*>(C + r0), v0);
            __stcs(reinterpret_cast<__half2*>(C + r1), v1);
        }
    }
}

// ---------------------------------------------------------------------------
// 4) y = fwht(z)/sqrt(M) * SU * Wscale. Reads fp16 z, writes fp32 y.
//    1024 threads x 16 elems; radix-16 x3 + radix-4.
// ---------------------------------------------------------------------------
__global__ void __launch_bounds__(1024)
fwht_y_kernel(const __half* __restrict__ z, float* __restrict__ y,
              const float* __restrict__ SU, const float* __restrict__ Wscale_p)
{
    extern __shared__ float s[];   // 16384 + 1024 floats (skewed)
    const int g = threadIdx.x;
    const int row = blockIdx.x;
    const __half2* zr = reinterpret_cast<const __half2*>(z + (size_t)row * M_DIM);
    float* yr = y + (size_t)row * M_DIM;
    float v[16];

    // round 1: stride 1, from gmem (fp16 -> fp32)
#pragma unroll
    for (int j = 0; j < 8; j++) {
        float2 f = __half22float2(zr[g * 8 + j]);
        v[2 * j] = f.x;
        v[2 * j + 1] = f.y;
    }
    fwht16(v);
#pragma unroll
    for (int j = 0; j < 16; j++) s[skew(g * 16 + j)] = v[j];
    __syncthreads();

    // round 2: stride 16
    {
        int base = (g >> 4) * 256 + (g & 15);
#pragma unroll
        for (int j = 0; j < 16; j++) v[j] = s[skew(base + j * 16)];
        fwht16(v);
#pragma unroll
        for (int j = 0; j < 16; j++) s[skew(base + j * 16)] = v[j];
    }
    __syncthreads();

    // round 3: stride 256
    {
        int base = (g >> 8) * 4096 + (g & 255);
#pragma unroll
        for (int j = 0; j < 16; j++) v[j] = s[skew(base + j * 256)];
        fwht16(v);
#pragma unroll
        for (int j = 0; j < 16; j++) s[skew(base + j * 256)] = v[j];
    }
    __syncthreads();

    // round 4: radix-4 at stride 4096, scale + write out
    float scb = (1.0f / sqrtf((float)M_DIM)) * __ldg(Wscale_p);
#pragma unroll
    for (int q = 0; q < 4; q++) {
        int idx = g + q * 1024;
        float a = s[skew(idx)];
        float b = s[skew(idx + 4096)];
        float c = s[skew(idx + 8192)];
        float d = s[skew(idx + 12288)];
        yr[idx]         = (a + b + c + d) * scb * SU[idx];
        yr[idx + 4096]  = (a - b + c - d) * scb * SU[idx + 4096];
        yr[idx + 8192]  = (a + b - c - d) * scb * SU[idx + 8192];
        yr[idx + 12288] = (a - b - c + d) * scb * SU[idx + 12288];
    }
}

// ---------------------------------------------------------------------------
// Launch
// ---------------------------------------------------------------------------
extern "C" void kernel_launch(void* const* d_in, const int* in_sizes, int n_in,
                              void* d_out, int out_size)
{
    const float* x   = (const float*)d_in[0];
    const int*   Q1  = (const int*)d_in[1];
    const int*   Q2  = (const int*)d_in[2];
    const float* SU  = (const float*)d_in[3];
    const float* SV  = (const float*)d_in[4];
    const float* cb1 = (const float*)d_in[5];
    const float* cb2 = (const float*)d_in[6];
    const float* Wsc = (const float*)d_in[7];
    const float* irs = (const float*)d_in[8];
    float* out = (float*)d_out;

    __half *t_p, *W_p, *z_p;
    cudaGetSymbolAddress((void**)&t_p, g_t);
    cudaGetSymbolAddress((void**)&W_p, g_W);
    cudaGetSymbolAddress((void**)&z_p, g_z);

    // 1) decode weights
    int total = M_DIM * (N_DIM / 8);
    decode_kernel<<<(total + 255) / 256, 256>>>(Q1, Q2, cb1, cb2, irs, W_p, total);

    // 2) input Hadamard transform
    fwht_x_kernel<<<T_DIM, 256>>>(x, SV, t_p);

    // 3) GEMM into fp16 z (96 KB dynamic smem, 2 CTAs/SM)
    int gemm_smem = 2 * STAGES * 128 * 8 * (int)sizeof(uint4);
    cudaFuncSetAttribute(gemm_mma_kernel,
                         cudaFuncAttributeMaxDynamicSharedMemorySize, gemm_smem);
    dim3 grid(T_DIM / BM, M_DIM / BN);
    gemm_mma_kernel<<<grid, 256, gemm_smem>>>(t_p, W_p, z_p);

    // 4) output Hadamard + scaling into d_out
    int ysmem = (M_DIM + 1024) * (int)sizeof(float);
    cudaFuncSetAttribute(fwht_y_kernel,
                         cudaFuncAttributeMaxDynamicSharedMemorySize, ysmem);
    fwht_y_kernel<<<T_DIM, 1024, ysmem>>>(z_p, out, SU, Wsc);
}